// round 15
// baseline (speedup 1.0000x reference)
#include <cuda_runtime.h>
#include <cuda_bf16.h>
#include <cstdint>

// Problem shape (fixed by the dataset)
#define B_ 8
#define T_ 4096
#define F_ 512
#define ROWS_ (B_ * T_)

// Scratch (no allocations allowed) — device globals.
__device__ float g_z[ROWS_];        // linear scores (monotone-equiv. for peaks)
__device__ int   g_idx[ROWS_];      // per batch: compact list of peak t's
__device__ int   g_hlens[B_];       // peak counts per batch

// ---------------------------------------------------------------------------
// Kernel 1: pure GEMV read stream. 512 threads = 16 warps; each warp does
// 4 rows (16 front-loaded LDG.128). Grid = ROWS_/64 = 512 blocks.
__global__ void __launch_bounds__(512) k_gemv(const float* __restrict__ feat,
                                              const float* __restrict__ W) {
    const int lane = threadIdx.x & 31;
    const int wid  = threadIdx.x >> 5;         // 0..15

    const float4* w4 = reinterpret_cast<const float4*>(W);
    float4 wreg[4];
#pragma unroll
    for (int i = 0; i < 4; i++) wreg[i] = w4[lane + i * 32];

    const int row0 = blockIdx.x * 64 + wid * 4;
    const float4* f0 = reinterpret_cast<const float4*>(feat + (size_t)(row0 + 0) * F_);
    const float4* f1 = reinterpret_cast<const float4*>(feat + (size_t)(row0 + 1) * F_);
    const float4* f2 = reinterpret_cast<const float4*>(feat + (size_t)(row0 + 2) * F_);
    const float4* f3 = reinterpret_cast<const float4*>(feat + (size_t)(row0 + 3) * F_);

    float4 a[4][4];
#pragma unroll
    for (int i = 0; i < 4; i++) {
        const int idx = lane + i * 32;
        a[0][i] = f0[idx];
        a[1][i] = f1[idx];
        a[2][i] = f2[idx];
        a[3][i] = f3[idx];
    }
    float s0 = 0.f, s1 = 0.f, s2 = 0.f, s3 = 0.f;
#pragma unroll
    for (int i = 0; i < 4; i++) {
        const float4 w = wreg[i];
        s0 += a[0][i].x * w.x + a[0][i].y * w.y + a[0][i].z * w.z + a[0][i].w * w.w;
        s1 += a[1][i].x * w.x + a[1][i].y * w.y + a[1][i].z * w.z + a[1][i].w * w.w;
        s2 += a[2][i].x * w.x + a[2][i].y * w.y + a[2][i].z * w.z + a[2][i].w * w.w;
        s3 += a[3][i].x * w.x + a[3][i].y * w.y + a[3][i].z * w.z + a[3][i].w * w.w;
    }
#pragma unroll
    for (int o = 16; o > 0; o >>= 1) {
        s0 += __shfl_down_sync(0xFFFFFFFFu, s0, o);
        s1 += __shfl_down_sync(0xFFFFFFFFu, s1, o);
        s2 += __shfl_down_sync(0xFFFFFFFFu, s2, o);
        s3 += __shfl_down_sync(0xFFFFFFFFu, s3, o);
    }
    if (lane == 0) {
        g_z[row0 + 0] = s0;
        g_z[row0 + 1] = s1;
        g_z[row0 + 2] = s2;
        g_z[row0 + 3] = s3;
    }
}

// ---------------------------------------------------------------------------
// Kernel 2: per-batch peak detect + stable scan -> compact gather list.
// One block of 1024 threads per batch.
__global__ void __launch_bounds__(1024) k_scan(float* __restrict__ out,
                                               int out_size) {
    const int b    = blockIdx.x;
    const int tid  = threadIdx.x;
    const int lane = tid & 31;
    const int wid  = tid >> 5;

    __shared__ int warp_sums[32];
    __shared__ int warp_incl[32];

    const float* zb = g_z + b * T_;
    const int t0 = tid * 4;                    // 1024 * 4 = 4096

    int flags[4];
    int cnt = 0;
#pragma unroll
    for (int k = 0; k < 4; k++) {
        int t = t0 + k;
        float c = zb[t];
        float l = (t > 0)      ? zb[t - 1] : c;
        float r = (t < T_ - 1) ? zb[t + 1] : c;
        flags[k] = (c >= l) & (c >= r);
        cnt += flags[k];
    }

    int v = cnt;
#pragma unroll
    for (int o = 1; o < 32; o <<= 1) {
        int n = __shfl_up_sync(0xFFFFFFFFu, v, o);
        if (lane >= o) v += n;
    }
    if (lane == 31) warp_sums[wid] = v;
    __syncthreads();
    if (wid == 0) {
        int s = warp_sums[lane];
#pragma unroll
        for (int o = 1; o < 32; o <<= 1) {
            int n = __shfl_up_sync(0xFFFFFFFFu, s, o);
            if (lane >= o) s += n;
        }
        warp_incl[lane] = s;
    }
    __syncthreads();

    int excl = (v - cnt) + (wid > 0 ? warp_incl[wid - 1] : 0);
#pragma unroll
    for (int k = 0; k < 4; k++) {
        int t = t0 + k;
        if (flags[k]) g_idx[b * T_ + excl] = t;    // i-th peak is position t
        excl += flags[k];
    }
    if (tid == 0) {
        int hl = warp_incl[31];
        g_hlens[b] = hl;
        if (out_size >= ROWS_ * F_ + B_)
            out[(size_t)ROWS_ * F_ + b] = (float)hl;
    }
}

// ---------------------------------------------------------------------------
// Kernel 3: destination-centric writer. Grid = ROWS_/4 = 8192 blocks of 512;
// each 128-thread group owns one dest row: i < hl[b] -> copy feat row
// g_idx[b][i] (L2-resident read), else zero. Coalesced sequential writes.
__global__ void __launch_bounds__(512) k_write(const float* __restrict__ feat,
                                               float* __restrict__ out) {
    const int tid = threadIdx.x;
    __shared__ int s_hl[B_];
    if (tid < B_) s_hl[tid] = g_hlens[tid];
    __syncthreads();

    const int row = blockIdx.x * 4 + (tid >> 7);   // dest row
    const int j   = tid & 127;                     // float4 index within row
    const int b   = row >> 12;                     // T_ = 4096
    const int i   = row & (T_ - 1);

    float4 v = make_float4(0.f, 0.f, 0.f, 0.f);
    if (i < s_hl[b]) {
        const int src = b * T_ + g_idx[row];
        v = reinterpret_cast<const float4*>(feat + (size_t)src * F_)[j];
    }
    reinterpret_cast<float4*>(out + (size_t)row * F_)[j] = v;
}

extern "C" void kernel_launch(void* const* d_in, const int* in_sizes, int n_in,
                              void* d_out, int out_size) {
    const float* feat = (const float*)d_in[0];
    const float* W    = (const float*)d_in[1];
    float* out        = (float*)d_out;

    k_gemv <<<ROWS_ / 64, 512>>>(feat, W);
    k_scan <<<B_, 1024>>>(out, out_size);
    k_write<<<ROWS_ / 4, 512>>>(feat, out);
}